// round 12
// baseline (speedup 1.0000x reference)
#include <cuda_runtime.h>
#include <math.h>

// ---------------------------------------------------------------------------
// Fixed scattering network: 2D Morlet scattering (J=4, L=4, N=128, B=64) + MLP
// R9: instruction-diet round.
//  - 128-entry twiddle table: every radix-8 twiddle (incl. conjugates and
//    i-rotated forms) is a direct W^k load; all per-pass twiddle ALU removed.
//  - radix-16 cores rewritten with packed f32x2 PTX (add/mul/fma.rn.f32x2):
//    complex = one 64-bit packed register; butterflies 8->6 / 4->2 instr.
// Structure unchanged from R7 (col-first inverse fused with gmem entry,
// coalesced forward exit), which measured best.
// ---------------------------------------------------------------------------

#define NB 64
#define NN 128
#define NPIX (NN*NN)
#define PITCH 129      // float2 pitch (odd -> conflict-free row AND col)
#define NT 1024

__device__ float2 g_Ihat[NB * NPIX];            // bitrev both dims
__device__ float2 g_U1hat[NB * 3 * 4 * NPIX];   // j1 in {0,1,2}
__device__ float  g_psi[16 * NPIX];             // bitrev both dims
__device__ float  g_s0[NB];
__device__ float  g_s1p[NB * 4 * 4];
__device__ float  g_s2p[NB * 6 * 16];

__constant__ int c_j1[6] = {0,0,0,1,1,2};
__constant__ int c_j2[6] = {1,2,3,2,3,3};

#define C_SQH 0.70710678118654752440f
#define C_S1 0.92387953251128675613f  // cos(pi/8)
#define C_S3 0.38268343236508977173f  // sin(pi/8)

static __device__ __forceinline__ float2 cadd(float2 a, float2 b){ return make_float2(a.x+b.x, a.y+b.y); }
static __device__ __forceinline__ float2 csub(float2 a, float2 b){ return make_float2(a.x-b.x, a.y-b.y); }
static __device__ __forceinline__ float2 cmul(float2 a, float2 b){ return make_float2(a.x*b.x-a.y*b.y, a.x*b.y+a.y*b.x); }
static __device__ __forceinline__ int brev7(int x){ return (int)(__brev((unsigned)x) >> 25); }

// ---------------------------------------------------------------------------
// packed f32x2 complex helpers (Blackwell)
// ---------------------------------------------------------------------------
typedef unsigned long long cplx;   // packed (re, im)

static __device__ __forceinline__ cplx cpack(float x, float y) {
    cplx r; asm("mov.b64 %0, {%1, %2};" : "=l"(r) : "f"(x), "f"(y)); return r;
}
static __device__ __forceinline__ float2 cunpack(cplx a) {
    float2 f; asm("mov.b64 {%0, %1}, %2;" : "=f"(f.x), "=f"(f.y) : "l"(a)); return f;
}
static __device__ __forceinline__ cplx cswap(cplx a) {
    cplx r;
    asm("{\n\t.reg .b32 lo, hi;\n\tmov.b64 {lo, hi}, %1;\n\tmov.b64 %0, {hi, lo};\n\t}"
        : "=l"(r) : "l"(a));
    return r;
}
static __device__ __forceinline__ cplx padd(cplx a, cplx b){ cplx r; asm("add.rn.f32x2 %0,%1,%2;":"=l"(r):"l"(a),"l"(b)); return r; }
static __device__ __forceinline__ cplx pmul(cplx a, cplx b){ cplx r; asm("mul.rn.f32x2 %0,%1,%2;":"=l"(r):"l"(a),"l"(b)); return r; }
static __device__ __forceinline__ cplx pfma(cplx a, cplx b, cplx c){ cplx r; asm("fma.rn.f32x2 %0,%1,%2,%3;":"=l"(r):"l"(a),"l"(b),"l"(c)); return r; }

// inverse (DIT) butterfly with twiddle w=(wx,wy): t = hi*w; lo'=lo+t; hi'=lo-t
static __device__ __forceinline__ void bfw_inv_p(cplx& lo, cplx& hi, float wx, float wy, cplx NEG1) {
    cplx t = pfma(cswap(hi), cpack(-wy, wy), pmul(hi, cpack(wx, wx)));
    cplx l = lo;
    lo = padd(l, t);
    hi = pfma(t, NEG1, l);
}
// forward (DIF) butterfly: d = lo-hi; lo'=lo+hi; hi' = d*w
static __device__ __forceinline__ void bfw_fwd_p(cplx& lo, cplx& hi, float wx, float wy, cplx NEG1) {
    cplx d = pfma(hi, NEG1, lo);
    lo = padd(lo, hi);
    hi = pfma(cswap(d), cpack(-wy, wy), pmul(d, cpack(wx, wx)));
}

// ---------------------------------------------------------------------------
struct Smem {
    float2* tile;  // [128][PITCH]
    float2* tw;    // [128] W_128^k, full period
    float*  rbuf;  // [32]
};
static __device__ __forceinline__ Smem get_smem() {
    extern __shared__ char sm[];
    Smem s;
    s.tile = (float2*)sm;
    s.tw   = s.tile + NN * PITCH;
    s.rbuf = (float*)(s.tw + 128);
    return s;
}
static __device__ __forceinline__ void init_tw(float2* tw) {
    if (threadIdx.x < 128) {
        float sv, cv;
        sincospif((float)threadIdx.x / 64.0f, &sv, &cv);
        tw[threadIdx.x] = make_float2(cv, -sv);   // W^k = e^{-2pi i k/128}
    }
}
// deterministic reduction (32 warps); result valid on thread 0
static __device__ __forceinline__ float block_reduce32(float v, float* rbuf) {
    #pragma unroll
    for (int o = 16; o > 0; o >>= 1) v += __shfl_down_sync(0xffffffffu, v, o);
    if ((threadIdx.x & 31) == 0) rbuf[threadIdx.x >> 5] = v;
    __syncthreads();
    float sres = 0.f;
    if (threadIdx.x == 0) {
        #pragma unroll
        for (int i = 0; i < 32; ++i) sres += rbuf[i];
    }
    __syncthreads();
    return sres;
}

// ---------------------------------------------------------------------------
// packed radix-16 cores (16 consecutive elements per thread)
// ---------------------------------------------------------------------------
static __device__ __forceinline__ void r16p_inv(cplx* x) {
    const cplx NEG1 = cpack(-1.f, -1.f);
    const cplx PMI  = cpack(-1.f, 1.f);    // pmul(cswap(a), PMI) = +i*a
    // stage h=1 (trivial)
    #pragma unroll
    for (int h = 0; h < 16; h += 2) { cplx l=x[h], t=x[h+1]; x[h]=padd(l,t); x[h+1]=pfma(t,NEG1,l); }
    // stage h=2 ({1, +i})
    #pragma unroll
    for (int h = 0; h < 16; h += 4) {
        { cplx l=x[h],   t=x[h+2];                 x[h]  =padd(l,t); x[h+2]=pfma(t,NEG1,l); }
        { cplx l=x[h+1], t=pmul(cswap(x[h+3]),PMI); x[h+1]=padd(l,t); x[h+3]=pfma(t,NEG1,l); }
    }
    // stage h=4 (W16c = {1,(sqh,sqh),+i,(-sqh,sqh)})
    #pragma unroll
    for (int h = 0; h < 16; h += 8) {
        { cplx l=x[h],   t=x[h+4];                 x[h]  =padd(l,t); x[h+4]=pfma(t,NEG1,l); }
        bfw_inv_p(x[h+1], x[h+5],  C_SQH, C_SQH, NEG1);
        { cplx l=x[h+2], t=pmul(cswap(x[h+6]),PMI); x[h+2]=padd(l,t); x[h+6]=pfma(t,NEG1,l); }
        bfw_inv_p(x[h+3], x[h+7], -C_SQH, C_SQH, NEG1);
    }
    // stage h=8 (W8c)
    { cplx l=x[0], t=x[8];                  x[0]=padd(l,t); x[8] =pfma(t,NEG1,l); }
    bfw_inv_p(x[1], x[9],   C_S1,  C_S3, NEG1);
    bfw_inv_p(x[2], x[10],  C_SQH, C_SQH, NEG1);
    bfw_inv_p(x[3], x[11],  C_S3,  C_S1, NEG1);
    { cplx l=x[4], t=pmul(cswap(x[12]),PMI); x[4]=padd(l,t); x[12]=pfma(t,NEG1,l); }
    bfw_inv_p(x[5], x[13], -C_S3,  C_S1, NEG1);
    bfw_inv_p(x[6], x[14], -C_SQH, C_SQH, NEG1);
    bfw_inv_p(x[7], x[15], -C_S1,  C_S3, NEG1);
}
static __device__ __forceinline__ void r16p_fwd(cplx* x) {
    const cplx NEG1 = cpack(-1.f, -1.f);
    const cplx PIM  = cpack(1.f, -1.f);    // pmul(cswap(a), PIM) = -i*a
    // stage h=8 (W8)
    { cplx l=x[0], h=x[8]; x[0]=padd(l,h); x[8]=pfma(h,NEG1,l); }
    bfw_fwd_p(x[1], x[9],   C_S1, -C_S3, NEG1);
    bfw_fwd_p(x[2], x[10],  C_SQH,-C_SQH, NEG1);
    bfw_fwd_p(x[3], x[11],  C_S3, -C_S1, NEG1);
    { cplx l=x[4], h=x[12]; cplx d=pfma(h,NEG1,l); x[4]=padd(l,h); x[12]=pmul(cswap(d),PIM); }
    bfw_fwd_p(x[5], x[13], -C_S3, -C_S1, NEG1);
    bfw_fwd_p(x[6], x[14], -C_SQH,-C_SQH, NEG1);
    bfw_fwd_p(x[7], x[15], -C_S1, -C_S3, NEG1);
    // stage h=4 (W16 = {1,(sqh,-sqh),-i,(-sqh,-sqh)})
    #pragma unroll
    for (int h = 0; h < 16; h += 8) {
        { cplx l=x[h], t=x[h+4]; x[h]=padd(l,t); x[h+4]=pfma(t,NEG1,l); }
        bfw_fwd_p(x[h+1], x[h+5],  C_SQH, -C_SQH, NEG1);
        { cplx l=x[h+2], t=x[h+6]; cplx d=pfma(t,NEG1,l); x[h+2]=padd(l,t); x[h+6]=pmul(cswap(d),PIM); }
        bfw_fwd_p(x[h+3], x[h+7], -C_SQH, -C_SQH, NEG1);
    }
    // stage h=2 ({1, -i})
    #pragma unroll
    for (int h = 0; h < 16; h += 4) {
        { cplx l=x[h],   t=x[h+2]; x[h]  =padd(l,t); x[h+2]=pfma(t,NEG1,l); }
        { cplx l=x[h+1], t=x[h+3]; cplx d=pfma(t,NEG1,l); x[h+1]=padd(l,t); x[h+3]=pmul(cswap(d),PIM); }
    }
    // stage h=1 (trivial)
    #pragma unroll
    for (int h = 0; h < 16; h += 2) { cplx l=x[h], t=x[h+1]; x[h]=padd(l,t); x[h+1]=pfma(t,NEG1,l); }
}

// ---------------------------------------------------------------------------
// radix-8 pass (smem<->smem, scalar, table-indexed twiddles)
// DIF halves {64,32,16} / DIT halves {16,32,64}; e = off + 16*j, lanes carry t
// ---------------------------------------------------------------------------
template<bool ROW>
static __device__ void pass_r8_fwd(float2* tile, const float2* tw) {
    #pragma unroll
    for (int k = 0; k < 2; ++k) {
        int q = threadIdx.x + k * NT;
        int t = q & 127, off = q >> 7;
        int base = ROW ? t * PITCH + off : off * PITCH + t;
        int str  = ROW ? 16 : 16 * PITCH;
        float2 x[8];
        #pragma unroll
        for (int j = 0; j < 8; ++j) x[j] = tile[base + j * str];
        float2 w1 = tw[off],       wA = tw[off + 16],
               wB = tw[off + 32],  wC = tw[off + 48];
        float2 w2 = tw[2*off],     w2n = tw[2*off + 32];
        float2 w4 = tw[4*off];
        float2 a, b;
        a=x[0]; b=x[4]; x[0]=cadd(a,b); x[4]=cmul(csub(a,b), w1);
        a=x[1]; b=x[5]; x[1]=cadd(a,b); x[5]=cmul(csub(a,b), wA);
        a=x[2]; b=x[6]; x[2]=cadd(a,b); x[6]=cmul(csub(a,b), wB);
        a=x[3]; b=x[7]; x[3]=cadd(a,b); x[7]=cmul(csub(a,b), wC);
        a=x[0]; b=x[2]; x[0]=cadd(a,b); x[2]=cmul(csub(a,b), w2);
        a=x[1]; b=x[3]; x[1]=cadd(a,b); x[3]=cmul(csub(a,b), w2n);
        a=x[4]; b=x[6]; x[4]=cadd(a,b); x[6]=cmul(csub(a,b), w2);
        a=x[5]; b=x[7]; x[5]=cadd(a,b); x[7]=cmul(csub(a,b), w2n);
        #pragma unroll
        for (int p = 0; p < 4; ++p) {
            a=x[2*p]; b=x[2*p+1];
            x[2*p]=cadd(a,b); x[2*p+1]=cmul(csub(a,b), w4);
        }
        #pragma unroll
        for (int j = 0; j < 8; ++j) tile[base + j * str] = x[j];
    }
}

// EPI: 0 store complex; 1 accumulate |y| only; 2 store (|y|*scale,0) + accumulate
template<bool ROW, int EPI>
static __device__ float pass_r8_inv(float2* tile, const float2* tw, float scale) {
    float acc = 0.f;
    #pragma unroll
    for (int k = 0; k < 2; ++k) {
        int q = threadIdx.x + k * NT;
        int t = q & 127, off = q >> 7;
        int base = ROW ? t * PITCH + off : off * PITCH + t;
        int str  = ROW ? 16 : 16 * PITCH;
        float2 x[8];
        #pragma unroll
        for (int j = 0; j < 8; ++j) x[j] = tile[base + j * str];
        // all conjugate/rotated twiddles are direct W^k loads:
        float2 w4c  = tw[(128 - 4*off) & 127];
        float2 w2c  = tw[(128 - 2*off) & 127];
        float2 w2ci = tw[96 - 2*off];
        float2 u0   = tw[(128 - off) & 127];
        float2 u1   = tw[112 - off];
        float2 u2   = tw[96 - off];
        float2 u3   = tw[80 - off];
        float2 a, bw;
        #pragma unroll
        for (int p = 0; p < 4; ++p) {
            a=x[2*p]; bw=cmul(x[2*p+1], w4c);
            x[2*p]=cadd(a,bw); x[2*p+1]=csub(a,bw);
        }
        a=x[0]; bw=cmul(x[2], w2c ); x[0]=cadd(a,bw); x[2]=csub(a,bw);
        a=x[1]; bw=cmul(x[3], w2ci); x[1]=cadd(a,bw); x[3]=csub(a,bw);
        a=x[4]; bw=cmul(x[6], w2c ); x[4]=cadd(a,bw); x[6]=csub(a,bw);
        a=x[5]; bw=cmul(x[7], w2ci); x[5]=cadd(a,bw); x[7]=csub(a,bw);
        a=x[0]; bw=cmul(x[4], u0); x[0]=cadd(a,bw); x[4]=csub(a,bw);
        a=x[1]; bw=cmul(x[5], u1); x[1]=cadd(a,bw); x[5]=csub(a,bw);
        a=x[2]; bw=cmul(x[6], u2); x[2]=cadd(a,bw); x[6]=csub(a,bw);
        a=x[3]; bw=cmul(x[7], u3); x[3]=cadd(a,bw); x[7]=csub(a,bw);
        if (EPI == 0) {
            #pragma unroll
            for (int j = 0; j < 8; ++j) tile[base + j * str] = x[j];
        } else {
            #pragma unroll
            for (int j = 0; j < 8; ++j) {
                float m = sqrtf(x[j].x * x[j].x + x[j].y * x[j].y);
                if (EPI == 2) {
                    m *= scale;
                    tile[base + j * str] = make_float2(m, 0.f);
                }
                acc += m;
            }
        }
    }
    return acc;
}

// ---------------------------------------------------------------------------
// r16 passes (1024 items = 128 transforms x 8 groups; exactly 1 per thread)
// ---------------------------------------------------------------------------
// inverse entry, column axis, fused with coalesced gmem read + PSI product
static __device__ void r16_col_inv_from_gmem(float2* tile,
                                             const float2* __restrict__ uh,
                                             const float*  __restrict__ ps) {
    int q = threadIdx.x;
    int t = q & 127, g = q >> 7;
    const cplx* u = (const cplx*)uh;
    cplx x[16];
    #pragma unroll
    for (int j = 0; j < 16; ++j) {
        int e = (16 * g + j) * NN + t;
        float p = ps[e];
        x[j] = pmul(u[e], cpack(p, p));
    }
    r16p_inv(x);
    cplx* tp = (cplx*)tile;
    int base = (16 * g) * PITCH + t;
    #pragma unroll
    for (int j = 0; j < 16; ++j) tp[base + j * PITCH] = x[j];
}
static __device__ void r16_row_inv(float2* tile) {
    int q = threadIdx.x;
    int t = q & 127, g = q >> 7;
    cplx* tp = (cplx*)tile;
    int base = t * PITCH + 16 * g;
    cplx x[16];
    #pragma unroll
    for (int j = 0; j < 16; ++j) x[j] = tp[base + j];
    r16p_inv(x);
    #pragma unroll
    for (int j = 0; j < 16; ++j) tp[base + j] = x[j];
}
static __device__ void r16_row_fwd(float2* tile) {
    int q = threadIdx.x;
    int t = q & 127, g = q >> 7;
    cplx* tp = (cplx*)tile;
    int base = t * PITCH + 16 * g;
    cplx x[16];
    #pragma unroll
    for (int j = 0; j < 16; ++j) x[j] = tp[base + j];
    r16p_fwd(x);
    #pragma unroll
    for (int j = 0; j < 16; ++j) tp[base + j] = x[j];
}
// forward exit: coalesced gmem write (lanes -> consecutive t)
static __device__ void r16_col_fwd_to_gmem(float2* tile, float2* __restrict__ dst) {
    int q = threadIdx.x;
    int t = q & 127, g = q >> 7;
    cplx* tp = (cplx*)tile;
    int base = (16 * g) * PITCH + t;
    cplx x[16];
    #pragma unroll
    for (int j = 0; j < 16; ++j) x[j] = tp[base + j * PITCH];
    r16p_fwd(x);
    cplx* d = (cplx*)dst;
    #pragma unroll
    for (int j = 0; j < 16; ++j) d[(16 * g + j) * NN + t] = x[j];
}

// ---------------------------------------------------------------------------
// K0: PSI in bit-reversed 2D order
// ---------------------------------------------------------------------------
static __device__ __forceinline__ float freqval(int i) {
    return (float)((i < 64) ? i : i - 128) * (6.283185307179586476925287e0f / 128.0f);
}
__global__ void k_psi() {
    int j = blockIdx.x >> 2, l = blockIdx.x & 3;
    float k0  = 2.356194490192345f / (float)(1 << j);
    float sg  = 0.8f * (float)(1 << j);
    float s2  = sg * sg;
    float th  = 0.7853981633974483f * (float)l;
    float k0x = k0 * cosf(th), k0y = k0 * sinf(th);
    float beta = expf(-0.5f * s2 * k0 * k0);
    float* dst = g_psi + (j * 4 + l) * NPIX;
    for (int e = threadIdx.x; e < NPIX; e += blockDim.x) {
        int r = e >> 7, c = e & 127;
        float kx = freqval(brev7(r));
        float ky = freqval(brev7(c));
        float dx = kx - k0x, dy = ky - k0y;
        float g1 = expf(-0.5f * s2 * (dx * dx + dy * dy));
        float g0 = expf(-0.5f * s2 * (kx * kx + ky * ky));
        dst[e] = g1 - beta * g0;
    }
}

// ---------------------------------------------------------------------------
// K1: I_hat = fft2(image) + s0.  grid = 64
// ---------------------------------------------------------------------------
__global__ __launch_bounds__(NT, 1)
void k_fft_image(const float* __restrict__ img) {
    Smem s = get_smem();
    init_tw(s.tw);
    const float* src = img + (size_t)blockIdx.x * NPIX;
    float acc = 0.f;
    #pragma unroll
    for (int k = 0; k < NPIX / NT; ++k) {
        int e = threadIdx.x + k * NT;
        float v = src[e];
        acc += v;
        s.tile[(e >> 7) * PITCH + (e & 127)] = make_float2(v, 0.f);
    }
    float tot = block_reduce32(acc, s.rbuf);   // syncs cover tw + tile
    if (threadIdx.x == 0) g_s0[blockIdx.x] = tot * (1.f / 16384.f);
    pass_r8_fwd<true>(s.tile, s.tw);  __syncthreads();
    r16_row_fwd(s.tile);              __syncthreads();
    pass_r8_fwd<false>(s.tile, s.tw); __syncthreads();
    r16_col_fwd_to_gmem(s.tile, g_Ihat + (size_t)blockIdx.x * NPIX);
}

// ---------------------------------------------------------------------------
// K2: u1 = |ifft2(I_hat*PSI)|/N^2; s1; u1_hat = fft2(u1) (j<3).  grid = 1024
// ---------------------------------------------------------------------------
__global__ __launch_bounds__(NT, 1)
void k_first() {
    Smem s = get_smem();
    init_tw(s.tw);
    int idx = blockIdx.x;
    int b = idx >> 4, j = (idx >> 2) & 3, l = idx & 3;
    const float2* ih = g_Ihat + (size_t)b * NPIX;
    const float*  ps = g_psi + (j * 4 + l) * NPIX;
    // inverse 2D, column axis first (entry fused with gmem product)
    r16_col_inv_from_gmem(s.tile, ih, ps);      __syncthreads();  // also orders tw
    pass_r8_inv<false, 0>(s.tile, s.tw, 0.f);   __syncthreads();
    r16_row_inv(s.tile);                        __syncthreads();
    float acc = pass_r8_inv<true, 2>(s.tile, s.tw, 1.f / 16384.f);
    float tot = block_reduce32(acc, s.rbuf);    // syncs cover (u,0) stores
    if (threadIdx.x == 0) g_s1p[(b * 4 + j) * 4 + l] = tot;
    if (j < 3) {
        pass_r8_fwd<true>(s.tile, s.tw);  __syncthreads();
        r16_row_fwd(s.tile);              __syncthreads();
        pass_r8_fwd<false>(s.tile, s.tw); __syncthreads();
        r16_col_fwd_to_gmem(s.tile, g_U1hat + ((size_t)(b * 3 + j) * 4 + l) * NPIX);
    }
}

// ---------------------------------------------------------------------------
// K3: s2 partial = sum |ifft2(u1_hat * PSI_{j2,l2})|.  grid = 6144
// ---------------------------------------------------------------------------
__global__ __launch_bounds__(NT, 1)
void k_second() {
    Smem s = get_smem();
    init_tw(s.tw);
    int idx = blockIdx.x;
    int b = idx / 96;
    int r0 = idx - b * 96;
    int p = r0 >> 4, l1 = (r0 >> 2) & 3, l2 = r0 & 3;
    int j1 = c_j1[p], j2 = c_j2[p];
    const float2* uh = g_U1hat + ((size_t)(b * 3 + j1) * 4 + l1) * NPIX;
    const float*  ps = g_psi + (j2 * 4 + l2) * NPIX;
    r16_col_inv_from_gmem(s.tile, uh, ps);      __syncthreads();  // also orders tw
    pass_r8_inv<false, 0>(s.tile, s.tw, 0.f);   __syncthreads();
    r16_row_inv(s.tile);                        __syncthreads();
    float acc = pass_r8_inv<true, 1>(s.tile, s.tw, 0.f);
    float tot = block_reduce32(acc, s.rbuf);
    if (threadIdx.x == 0) g_s2p[(b * 6 + p) * 16 + (l1 * 4 + l2)] = tot * (1.f / 16384.f);
}

// ---------------------------------------------------------------------------
// K4: finalize + MLP
// ---------------------------------------------------------------------------
__global__ void k_final(const float* __restrict__ fc1w, const float* __restrict__ fc1b,
                        const float* __restrict__ fc2w, const float* __restrict__ fc2b,
                        float* __restrict__ out) {
    int b = threadIdx.x;
    if (b >= NB) return;
    float coeffs[11];
    coeffs[0] = g_s0[b];
    #pragma unroll
    for (int j = 0; j < 4; ++j) {
        float s = 0.f;
        #pragma unroll
        for (int l = 0; l < 4; ++l) s += g_s1p[(b * 4 + j) * 4 + l];
        coeffs[1 + j] = s * (1.f / 65536.f);
    }
    #pragma unroll
    for (int p = 0; p < 6; ++p) {
        float s = 0.f;
        #pragma unroll
        for (int i = 0; i < 16; ++i) s += g_s2p[(b * 6 + p) * 16 + i];
        coeffs[5 + p] = s * (1.f / (16.f * 16384.f));
    }
    float h[4];
    #pragma unroll
    for (int i = 0; i < 4; ++i) {
        float a = fc1b[i];
        #pragma unroll
        for (int k = 0; k < 11; ++k) a += coeffs[k] * fc1w[i * 11 + k];
        h[i] = fmaxf(a, 0.f);
    }
    #pragma unroll
    for (int o = 0; o < 10; ++o) {
        float a = fc2b[o];
        #pragma unroll
        for (int i = 0; i < 4; ++i) a += h[i] * fc2w[o * 4 + i];
        out[b * 10 + o] = 1.f / (1.f + expf(-a));
    }
}

// ---------------------------------------------------------------------------
extern "C" void kernel_launch(void* const* d_in, const int* in_sizes, int n_in,
                              void* d_out, int out_size) {
    (void)in_sizes; (void)n_in; (void)out_size;
    const float* img  = (const float*)d_in[0];
    const float* fc1w = (const float*)d_in[1];
    const float* fc1b = (const float*)d_in[2];
    const float* fc2w = (const float*)d_in[3];
    const float* fc2b = (const float*)d_in[4];
    float* out = (float*)d_out;

    const int smem_sz = NN * PITCH * (int)sizeof(float2)
                      + 128 * (int)sizeof(float2) + 32 * (int)sizeof(float);
    cudaFuncSetAttribute(k_fft_image, cudaFuncAttributeMaxDynamicSharedMemorySize, smem_sz);
    cudaFuncSetAttribute(k_first,     cudaFuncAttributeMaxDynamicSharedMemorySize, smem_sz);
    cudaFuncSetAttribute(k_second,    cudaFuncAttributeMaxDynamicSharedMemorySize, smem_sz);

    k_psi<<<16, 256>>>();
    k_fft_image<<<NB, NT, smem_sz>>>(img);
    k_first<<<NB * 16, NT, smem_sz>>>();
    k_second<<<NB * 96, NT, smem_sz>>>();
    k_final<<<1, 64>>>(fc1w, fc1b, fc2w, fc2b, out);
}

// round 15
// speedup vs baseline: 1.1396x; 1.1396x over previous
#include <cuda_runtime.h>
#include <math.h>

// ---------------------------------------------------------------------------
// Fixed scattering network: 2D Morlet scattering (J=4, L=4, N=128, B=64) + MLP
// R12: revert to R7 structure (measured best: col-first inverse fused with
// coalesced gmem entry, coalesced forward exit, scalar FFMA butterflies,
// per-pass computed twiddles). Single change: magnitude |z| uses
// sqrt.approx.f32 (1 MUFU op) instead of IEEE sqrtf's multi-instr sequence.
// ---------------------------------------------------------------------------

#define NB 64
#define NN 128
#define NPIX (NN*NN)
#define PITCH 129      // float2 pitch (odd -> conflict-free row AND col)
#define NT 1024

__device__ float2 g_Ihat[NB * NPIX];            // bitrev both dims
__device__ float2 g_U1hat[NB * 3 * 4 * NPIX];   // j1 in {0,1,2}
__device__ float  g_psi[16 * NPIX];             // bitrev both dims
__device__ float  g_s0[NB];
__device__ float  g_s1p[NB * 4 * 4];
__device__ float  g_s2p[NB * 6 * 16];

__constant__ int c_j1[6] = {0,0,0,1,1,2};
__constant__ int c_j2[6] = {1,2,3,2,3,3};

#define C_SQH 0.70710678118654752440f
#define C_S1 0.92387953251128675613f  // cos(pi/8)
#define C_S3 0.38268343236508977173f  // sin(pi/8)

static __device__ __forceinline__ float2 cadd(float2 a, float2 b){ return make_float2(a.x+b.x, a.y+b.y); }
static __device__ __forceinline__ float2 csub(float2 a, float2 b){ return make_float2(a.x-b.x, a.y-b.y); }
static __device__ __forceinline__ float2 cmul(float2 a, float2 b){ return make_float2(a.x*b.x-a.y*b.y, a.x*b.y+a.y*b.x); }
static __device__ __forceinline__ float2 cconj(float2 a){ return make_float2(a.x, -a.y); }
static __device__ __forceinline__ float2 mul_i(float2 a){ return make_float2(-a.y, a.x); }
static __device__ __forceinline__ float2 mul_negi(float2 a){ return make_float2(a.y, -a.x); }
static __device__ __forceinline__ int brev7(int x){ return (int)(__brev((unsigned)x) >> 25); }

// single-MUFU magnitude sqrt (exact at 0, ~1 ulp; tolerance is 1e-3)
static __device__ __forceinline__ float fast_sqrt(float s) {
    float r; asm("sqrt.approx.f32 %0, %1;" : "=f"(r) : "f"(s)); return r;
}

// ---------------------------------------------------------------------------
struct Smem {
    float2* tile;  // [128][PITCH]
    float2* tw;    // [64] W_128^k
    float*  rbuf;  // [32]
};
static __device__ __forceinline__ Smem get_smem() {
    extern __shared__ char sm[];
    Smem s;
    s.tile = (float2*)sm;
    s.tw   = s.tile + NN * PITCH;
    s.rbuf = (float*)(s.tw + 64);
    return s;
}
static __device__ __forceinline__ void init_tw(float2* tw) {
    if (threadIdx.x < 64) {
        float sv, cv;
        sincospif((float)threadIdx.x / 64.0f, &sv, &cv);
        tw[threadIdx.x] = make_float2(cv, -sv);
    }
}
// deterministic reduction (32 warps); result valid on thread 0
static __device__ __forceinline__ float block_reduce32(float v, float* rbuf) {
    #pragma unroll
    for (int o = 16; o > 0; o >>= 1) v += __shfl_down_sync(0xffffffffu, v, o);
    if ((threadIdx.x & 31) == 0) rbuf[threadIdx.x >> 5] = v;
    __syncthreads();
    float sres = 0.f;
    if (threadIdx.x == 0) {
        #pragma unroll
        for (int i = 0; i < 32; ++i) sres += rbuf[i];
    }
    __syncthreads();
    return sres;
}

// ---------------------------------------------------------------------------
// radix-16 butterfly cores (16 consecutive elements, constant twiddles)
// ---------------------------------------------------------------------------
static __device__ __forceinline__ void r16_core_fwd(float2* x) {
    const float2 W8[8] = {{1.f,0.f},{C_S1,-C_S3},{C_SQH,-C_SQH},{C_S3,-C_S1},
                          {0.f,-1.f},{-C_S3,-C_S1},{-C_SQH,-C_SQH},{-C_S1,-C_S3}};
    const float2 W16[4] = {{1.f,0.f},{C_SQH,-C_SQH},{0.f,-1.f},{-C_SQH,-C_SQH}};
    float2 a, b;
    #pragma unroll
    for (int j = 0; j < 8; ++j) {
        a=x[j]; b=x[j+8]; x[j]=cadd(a,b); x[j+8]=cmul(csub(a,b), W8[j]);
    }
    #pragma unroll
    for (int h = 0; h < 16; h += 8)
        #pragma unroll
        for (int j = 0; j < 4; ++j) {
            a=x[h+j]; b=x[h+j+4]; x[h+j]=cadd(a,b); x[h+j+4]=cmul(csub(a,b), W16[j]);
        }
    #pragma unroll
    for (int h = 0; h < 16; h += 4) {
        a=x[h];   b=x[h+2]; x[h]  =cadd(a,b); x[h+2]=csub(a,b);
        a=x[h+1]; b=x[h+3]; x[h+1]=cadd(a,b); x[h+3]=mul_negi(csub(a,b));
    }
    #pragma unroll
    for (int h = 0; h < 16; h += 2) {
        a=x[h]; b=x[h+1]; x[h]=cadd(a,b); x[h+1]=csub(a,b);
    }
}
static __device__ __forceinline__ void r16_core_inv(float2* x) {
    const float2 W16c[4] = {{1.f,0.f},{C_SQH,C_SQH},{0.f,1.f},{-C_SQH,C_SQH}};
    const float2 W8c[8]  = {{1.f,0.f},{C_S1,C_S3},{C_SQH,C_SQH},{C_S3,C_S1},
                            {0.f,1.f},{-C_S3,C_S1},{-C_SQH,C_SQH},{-C_S1,C_S3}};
    float2 a, bw;
    #pragma unroll
    for (int h = 0; h < 16; h += 2) {
        a=x[h]; bw=x[h+1]; x[h]=cadd(a,bw); x[h+1]=csub(a,bw);
    }
    #pragma unroll
    for (int h = 0; h < 16; h += 4) {
        a=x[h];   bw=x[h+2];        x[h]  =cadd(a,bw);  x[h+2]=csub(a,bw);
        a=x[h+1]; bw=mul_i(x[h+3]); x[h+1]=cadd(a,bw);  x[h+3]=csub(a,bw);
    }
    #pragma unroll
    for (int h = 0; h < 16; h += 8)
        #pragma unroll
        for (int j = 0; j < 4; ++j) {
            a=x[h+j]; bw=cmul(x[h+j+4], W16c[j]);
            x[h+j]=cadd(a,bw); x[h+j+4]=csub(a,bw);
        }
    #pragma unroll
    for (int j = 0; j < 8; ++j) {
        a=x[j]; bw=cmul(x[j+8], W8c[j]);
        x[j]=cadd(a,bw); x[j+8]=csub(a,bw);
    }
}

// ---------------------------------------------------------------------------
// radix-8 pass (smem<->smem): DIF halves {64,32,16} / DIT halves {16,32,64}
// elements e = off + 16*j; lanes carry transform index t (conflict-free)
// ---------------------------------------------------------------------------
template<bool ROW>
static __device__ void pass_r8_fwd(float2* tile, const float2* tw) {
    #pragma unroll
    for (int k = 0; k < 2; ++k) {
        int q = threadIdx.x + k * NT;
        int t = q & 127, off = q >> 7;
        int base = ROW ? t * PITCH + off : off * PITCH + t;
        int str  = ROW ? 16 : 16 * PITCH;
        float2 x[8];
        #pragma unroll
        for (int j = 0; j < 8; ++j) x[j] = tile[base + j * str];
        float2 w1 = tw[off], w2 = tw[2*off], w4 = tw[4*off];
        float2 w1c1 = cmul(w1, make_float2(C_SQH, -C_SQH));
        float2 w1c2 = mul_negi(w1);
        float2 w1c3 = cmul(w1, make_float2(-C_SQH, -C_SQH));
        float2 a, b;
        a=x[0]; b=x[4]; x[0]=cadd(a,b); x[4]=cmul(csub(a,b), w1);
        a=x[1]; b=x[5]; x[1]=cadd(a,b); x[5]=cmul(csub(a,b), w1c1);
        a=x[2]; b=x[6]; x[2]=cadd(a,b); x[6]=cmul(csub(a,b), w1c2);
        a=x[3]; b=x[7]; x[3]=cadd(a,b); x[7]=cmul(csub(a,b), w1c3);
        float2 w2n = mul_negi(w2);
        a=x[0]; b=x[2]; x[0]=cadd(a,b); x[2]=cmul(csub(a,b), w2);
        a=x[1]; b=x[3]; x[1]=cadd(a,b); x[3]=cmul(csub(a,b), w2n);
        a=x[4]; b=x[6]; x[4]=cadd(a,b); x[6]=cmul(csub(a,b), w2);
        a=x[5]; b=x[7]; x[5]=cadd(a,b); x[7]=cmul(csub(a,b), w2n);
        #pragma unroll
        for (int p = 0; p < 4; ++p) {
            a=x[2*p]; b=x[2*p+1];
            x[2*p]=cadd(a,b); x[2*p+1]=cmul(csub(a,b), w4);
        }
        #pragma unroll
        for (int j = 0; j < 8; ++j) tile[base + j * str] = x[j];
    }
}

// EPI: 0 store complex; 1 accumulate |y| only; 2 store (|y|*scale,0) + accumulate
template<bool ROW, int EPI>
static __device__ float pass_r8_inv(float2* tile, const float2* tw, float scale) {
    float acc = 0.f;
    #pragma unroll
    for (int k = 0; k < 2; ++k) {
        int q = threadIdx.x + k * NT;
        int t = q & 127, off = q >> 7;
        int base = ROW ? t * PITCH + off : off * PITCH + t;
        int str  = ROW ? 16 : 16 * PITCH;
        float2 x[8];
        #pragma unroll
        for (int j = 0; j < 8; ++j) x[j] = tile[base + j * str];
        float2 w1c = cconj(tw[off]), w2c = cconj(tw[2*off]), w4c = cconj(tw[4*off]);
        float2 a, bw;
        #pragma unroll
        for (int p = 0; p < 4; ++p) {
            a=x[2*p]; bw=cmul(x[2*p+1], w4c);
            x[2*p]=cadd(a,bw); x[2*p+1]=csub(a,bw);
        }
        float2 w2ci = mul_i(w2c);
        a=x[0]; bw=cmul(x[2], w2c ); x[0]=cadd(a,bw); x[2]=csub(a,bw);
        a=x[1]; bw=cmul(x[3], w2ci); x[1]=cadd(a,bw); x[3]=csub(a,bw);
        a=x[4]; bw=cmul(x[6], w2c ); x[4]=cadd(a,bw); x[6]=csub(a,bw);
        a=x[5]; bw=cmul(x[7], w2ci); x[5]=cadd(a,bw); x[7]=csub(a,bw);
        float2 u0 = w1c;
        float2 u1 = cmul(w1c, make_float2(C_SQH, C_SQH));
        float2 u2 = mul_i(w1c);
        float2 u3 = cmul(w1c, make_float2(-C_SQH, C_SQH));
        a=x[0]; bw=cmul(x[4], u0); x[0]=cadd(a,bw); x[4]=csub(a,bw);
        a=x[1]; bw=cmul(x[5], u1); x[1]=cadd(a,bw); x[5]=csub(a,bw);
        a=x[2]; bw=cmul(x[6], u2); x[2]=cadd(a,bw); x[6]=csub(a,bw);
        a=x[3]; bw=cmul(x[7], u3); x[3]=cadd(a,bw); x[7]=csub(a,bw);
        if (EPI == 0) {
            #pragma unroll
            for (int j = 0; j < 8; ++j) tile[base + j * str] = x[j];
        } else {
            #pragma unroll
            for (int j = 0; j < 8; ++j) {
                float m = fast_sqrt(x[j].x * x[j].x + x[j].y * x[j].y);
                if (EPI == 2) {
                    m *= scale;
                    tile[base + j * str] = make_float2(m, 0.f);
                }
                acc += m;
            }
        }
    }
    return acc;
}

// ---------------------------------------------------------------------------
// r16 passes (1024 items = 128 transforms x 8 groups; exactly 1 per thread)
// ---------------------------------------------------------------------------
// inverse entry, column axis, fused with coalesced gmem read + PSI product:
// thread (t,g) reads elements r = 16g+j of column t; lanes span consecutive t
// -> each load instruction is a 256B coalesced transaction.
static __device__ void r16_col_inv_from_gmem(float2* tile,
                                             const float2* __restrict__ uh,
                                             const float*  __restrict__ ps) {
    int q = threadIdx.x;
    int t = q & 127, g = q >> 7;
    float2 x[16];
    #pragma unroll
    for (int j = 0; j < 16; ++j) {
        int e = (16 * g + j) * NN + t;
        float2 v = uh[e];
        float p = ps[e];
        x[j] = make_float2(v.x * p, v.y * p);
    }
    r16_core_inv(x);
    int base = (16 * g) * PITCH + t;
    #pragma unroll
    for (int j = 0; j < 16; ++j) tile[base + j * PITCH] = x[j];
}
static __device__ void r16_row_inv(float2* tile) {
    int q = threadIdx.x;
    int t = q & 127, g = q >> 7;
    int base = t * PITCH + 16 * g;
    float2 x[16];
    #pragma unroll
    for (int j = 0; j < 16; ++j) x[j] = tile[base + j];
    r16_core_inv(x);
    #pragma unroll
    for (int j = 0; j < 16; ++j) tile[base + j] = x[j];
}
static __device__ void r16_row_fwd(float2* tile) {
    int q = threadIdx.x;
    int t = q & 127, g = q >> 7;
    int base = t * PITCH + 16 * g;
    float2 x[16];
    #pragma unroll
    for (int j = 0; j < 16; ++j) x[j] = tile[base + j];
    r16_core_fwd(x);
    #pragma unroll
    for (int j = 0; j < 16; ++j) tile[base + j] = x[j];
}
// forward exit: r16 col core, coalesced gmem write (lanes -> consecutive t)
static __device__ void r16_col_fwd_to_gmem(float2* tile, float2* __restrict__ dst) {
    int q = threadIdx.x;
    int t = q & 127, g = q >> 7;
    int base = (16 * g) * PITCH + t;
    float2 x[16];
    #pragma unroll
    for (int j = 0; j < 16; ++j) x[j] = tile[base + j * PITCH];
    r16_core_fwd(x);
    #pragma unroll
    for (int j = 0; j < 16; ++j) dst[(16 * g + j) * NN + t] = x[j];
}

// ---------------------------------------------------------------------------
// K0: PSI in bit-reversed 2D order
// ---------------------------------------------------------------------------
static __device__ __forceinline__ float freqval(int i) {
    return (float)((i < 64) ? i : i - 128) * (6.283185307179586476925287e0f / 128.0f);
}
__global__ void k_psi() {
    int j = blockIdx.x >> 2, l = blockIdx.x & 3;
    float k0  = 2.356194490192345f / (float)(1 << j);
    float sg  = 0.8f * (float)(1 << j);
    float s2  = sg * sg;
    float th  = 0.7853981633974483f * (float)l;
    float k0x = k0 * cosf(th), k0y = k0 * sinf(th);
    float beta = expf(-0.5f * s2 * k0 * k0);
    float* dst = g_psi + (j * 4 + l) * NPIX;
    for (int e = threadIdx.x; e < NPIX; e += blockDim.x) {
        int r = e >> 7, c = e & 127;
        float kx = freqval(brev7(r));
        float ky = freqval(brev7(c));
        float dx = kx - k0x, dy = ky - k0y;
        float g1 = expf(-0.5f * s2 * (dx * dx + dy * dy));
        float g0 = expf(-0.5f * s2 * (kx * kx + ky * ky));
        dst[e] = g1 - beta * g0;
    }
}

// ---------------------------------------------------------------------------
// K1: I_hat = fft2(image) + s0.  grid = 64
// ---------------------------------------------------------------------------
__global__ __launch_bounds__(NT, 1)
void k_fft_image(const float* __restrict__ img) {
    Smem s = get_smem();
    init_tw(s.tw);
    const float* src = img + (size_t)blockIdx.x * NPIX;
    float acc = 0.f;
    #pragma unroll
    for (int k = 0; k < NPIX / NT; ++k) {
        int e = threadIdx.x + k * NT;
        float v = src[e];
        acc += v;
        s.tile[(e >> 7) * PITCH + (e & 127)] = make_float2(v, 0.f);
    }
    float tot = block_reduce32(acc, s.rbuf);   // syncs cover tw + tile
    if (threadIdx.x == 0) g_s0[blockIdx.x] = tot * (1.f / 16384.f);
    pass_r8_fwd<true>(s.tile, s.tw);  __syncthreads();
    r16_row_fwd(s.tile);              __syncthreads();
    pass_r8_fwd<false>(s.tile, s.tw); __syncthreads();
    r16_col_fwd_to_gmem(s.tile, g_Ihat + (size_t)blockIdx.x * NPIX);
}

// ---------------------------------------------------------------------------
// K2: u1 = |ifft2(I_hat*PSI)|/N^2; s1; u1_hat = fft2(u1) (j<3).  grid = 1024
// ---------------------------------------------------------------------------
__global__ __launch_bounds__(NT, 1)
void k_first() {
    Smem s = get_smem();
    init_tw(s.tw);
    int idx = blockIdx.x;
    int b = idx >> 4, j = (idx >> 2) & 3, l = idx & 3;
    const float2* ih = g_Ihat + (size_t)b * NPIX;
    const float*  ps = g_psi + (j * 4 + l) * NPIX;
    // inverse 2D, column axis first (entry fused with gmem product)
    r16_col_inv_from_gmem(s.tile, ih, ps);      __syncthreads();  // also orders tw
    pass_r8_inv<false, 0>(s.tile, s.tw, 0.f);   __syncthreads();
    r16_row_inv(s.tile);                        __syncthreads();
    float acc = pass_r8_inv<true, 2>(s.tile, s.tw, 1.f / 16384.f);
    float tot = block_reduce32(acc, s.rbuf);    // syncs cover (u,0) stores
    if (threadIdx.x == 0) g_s1p[(b * 4 + j) * 4 + l] = tot;
    if (j < 3) {
        pass_r8_fwd<true>(s.tile, s.tw);  __syncthreads();
        r16_row_fwd(s.tile);              __syncthreads();
        pass_r8_fwd<false>(s.tile, s.tw); __syncthreads();
        r16_col_fwd_to_gmem(s.tile, g_U1hat + ((size_t)(b * 3 + j) * 4 + l) * NPIX);
    }
}

// ---------------------------------------------------------------------------
// K3: s2 partial = sum |ifft2(u1_hat * PSI_{j2,l2})|.  grid = 6144
// ---------------------------------------------------------------------------
__global__ __launch_bounds__(NT, 1)
void k_second() {
    Smem s = get_smem();
    init_tw(s.tw);
    int idx = blockIdx.x;
    int b = idx / 96;
    int r0 = idx - b * 96;
    int p = r0 >> 4, l1 = (r0 >> 2) & 3, l2 = r0 & 3;
    int j1 = c_j1[p], j2 = c_j2[p];
    const float2* uh = g_U1hat + ((size_t)(b * 3 + j1) * 4 + l1) * NPIX;
    const float*  ps = g_psi + (j2 * 4 + l2) * NPIX;
    r16_col_inv_from_gmem(s.tile, uh, ps);      __syncthreads();  // also orders tw
    pass_r8_inv<false, 0>(s.tile, s.tw, 0.f);   __syncthreads();
    r16_row_inv(s.tile);                        __syncthreads();
    float acc = pass_r8_inv<true, 1>(s.tile, s.tw, 0.f);
    float tot = block_reduce32(acc, s.rbuf);
    if (threadIdx.x == 0) g_s2p[(b * 6 + p) * 16 + (l1 * 4 + l2)] = tot * (1.f / 16384.f);
}

// ---------------------------------------------------------------------------
// K4: finalize + MLP
// ---------------------------------------------------------------------------
__global__ void k_final(const float* __restrict__ fc1w, const float* __restrict__ fc1b,
                        const float* __restrict__ fc2w, const float* __restrict__ fc2b,
                        float* __restrict__ out) {
    int b = threadIdx.x;
    if (b >= NB) return;
    float coeffs[11];
    coeffs[0] = g_s0[b];
    #pragma unroll
    for (int j = 0; j < 4; ++j) {
        float s = 0.f;
        #pragma unroll
        for (int l = 0; l < 4; ++l) s += g_s1p[(b * 4 + j) * 4 + l];
        coeffs[1 + j] = s * (1.f / 65536.f);
    }
    #pragma unroll
    for (int p = 0; p < 6; ++p) {
        float s = 0.f;
        #pragma unroll
        for (int i = 0; i < 16; ++i) s += g_s2p[(b * 6 + p) * 16 + i];
        coeffs[5 + p] = s * (1.f / (16.f * 16384.f));
    }
    float h[4];
    #pragma unroll
    for (int i = 0; i < 4; ++i) {
        float a = fc1b[i];
        #pragma unroll
        for (int k = 0; k < 11; ++k) a += coeffs[k] * fc1w[i * 11 + k];
        h[i] = fmaxf(a, 0.f);
    }
    #pragma unroll
    for (int o = 0; o < 10; ++o) {
        float a = fc2b[o];
        #pragma unroll
        for (int i = 0; i < 4; ++i) a += h[i] * fc2w[o * 4 + i];
        out[b * 10 + o] = 1.f / (1.f + expf(-a));
    }
}

// ---------------------------------------------------------------------------
extern "C" void kernel_launch(void* const* d_in, const int* in_sizes, int n_in,
                              void* d_out, int out_size) {
    (void)in_sizes; (void)n_in; (void)out_size;
    const float* img  = (const float*)d_in[0];
    const float* fc1w = (const float*)d_in[1];
    const float* fc1b = (const float*)d_in[2];
    const float* fc2w = (const float*)d_in[3];
    const float* fc2b = (const float*)d_in[4];
    float* out = (float*)d_out;

    const int smem_sz = NN * PITCH * (int)sizeof(float2)
                      + 64 * (int)sizeof(float2) + 32 * (int)sizeof(float);
    cudaFuncSetAttribute(k_fft_image, cudaFuncAttributeMaxDynamicSharedMemorySize, smem_sz);
    cudaFuncSetAttribute(k_first,     cudaFuncAttributeMaxDynamicSharedMemorySize, smem_sz);
    cudaFuncSetAttribute(k_second,    cudaFuncAttributeMaxDynamicSharedMemorySize, smem_sz);

    k_psi<<<16, 256>>>();
    k_fft_image<<<NB, NT, smem_sz>>>(img);
    k_first<<<NB * 16, NT, smem_sz>>>();
    k_second<<<NB * 96, NT, smem_sz>>>();
    k_final<<<1, 64>>>(fc1w, fc1b, fc2w, fc2b, out);
}